// round 6
// baseline (speedup 1.0000x reference)
#include <cuda_runtime.h>

#define FM_H 38
#define FM_W 50
#define N_ROI 512
#define POOL 7

__device__ __forceinline__ float4 quad4(float4 a, float4 b, float4 c, float4 d,
                                        float w0, float w1, float w2, float w3) {
    float4 r;
    r.x = fmaf(d.x, w3, fmaf(c.x, w2, fmaf(b.x, w1, a.x * w0)));
    r.y = fmaf(d.y, w3, fmaf(c.y, w2, fmaf(b.y, w1, a.y * w0)));
    r.z = fmaf(d.z, w3, fmaf(c.z, w2, fmaf(b.z, w1, a.z * w0)));
    r.w = fmaf(d.w, w3, fmaf(c.w, w2, fmaf(b.w, w1, a.w * w0)));
    return r;
}

__device__ __forceinline__ float4 max4(float4 a, float4 b) {
    float4 r;
    r.x = fmaxf(a.x, b.x);
    r.y = fmaxf(a.y, b.y);
    r.z = fmaxf(a.z, b.z);
    r.w = fmaxf(a.w, b.w);
    return r;
}

// One pooled cell: load NR distinct rows x NC distinct cols (all
// unconditional, batched), then 4 bilinear points via scalar weights.
// Pair-a uses loaded rows (0,1) / cols (0,1); pair-b uses rows (PB,PB+1),
// cols (CB,CB+1).
template <int NR, int PB, int NC, int CB>
__device__ __forceinline__ void cell_compute(
    const float4* __restrict__ fmt, float4* __restrict__ op,
    const int* ro, const int* co,
    float waP, float waQ, float wbP, float wbQ,
    float uxa, float wxa, float uxb, float wxb)
{
    float4 G[NR][NC];
#pragma unroll
    for (int r = 0; r < NR; ++r)
#pragma unroll
        for (int c = 0; c < NC; ++c)
            G[r][c] = fmt[(ro[r] + co[c]) * 128];

    const float4 s_aa = quad4(G[0][0],  G[0][1],    G[1][0],    G[1][1],
                              waP * uxa, waP * wxa, waQ * uxa, waQ * wxa);
    const float4 s_ab = quad4(G[0][CB], G[0][CB+1], G[1][CB],   G[1][CB+1],
                              waP * uxb, waP * wxb, waQ * uxb, waQ * wxb);
    const float4 s_ba = quad4(G[PB][0], G[PB][1],   G[PB+1][0], G[PB+1][1],
                              wbP * uxa, wbP * wxa, wbQ * uxa, wbQ * wxa);
    const float4 s_bb = quad4(G[PB][CB], G[PB][CB+1], G[PB+1][CB], G[PB+1][CB+1],
                              wbP * uxb, wbP * wxb, wbQ * uxb, wbQ * wxb);

    *op = max4(max4(s_aa, s_ab), max4(s_ba, s_bb));
}

// Streams the 7 pooled cells of one pooled row. Row set (NR,PB) fixed per
// block; per cell a block-uniform 3-way branch picks the distinct-column
// count NC in {2,3,4}.
template <int NR, int PB>
__device__ __forceinline__ void run_row(
    const float4* __restrict__ fmt, float4* __restrict__ outp,
    float x1n, float dx,
    int r0, int r1, int r2, int r3,
    float waP, float waQ, float wbP, float wbQ)
{
    int ro[4] = {r0, r1, r2, r3};

#pragma unroll
    for (int px = 0; px < POOL; ++px) {
        int x0a, x1a, x0b, x1b;
        float wxa, wxb;
        {
            const float txa = (float)(2 * px) * (1.0f / 13.0f);
            const float xsa = (x1n + txa * dx) * (float)(FM_W - 1);
            const float xfa = floorf(xsa);
            int x0 = (int)xfa; x0 = min(max(x0, 0), FM_W - 1);
            x0a = x0; x1a = min(x0 + 1, FM_W - 1); wxa = xsa - xfa;

            const float txb = (float)(2 * px + 1) * (1.0f / 13.0f);
            const float xsb = (x1n + txb * dx) * (float)(FM_W - 1);
            const float xfb = floorf(xsb);
            int x1 = (int)xfb; x1 = min(max(x1, 0), FM_W - 1);
            x0b = x1; x1b = min(x1 + 1, FM_W - 1); wxb = xsb - xfb;
        }
        const float uxa = 1.0f - wxa;
        const float uxb = 1.0f - wxb;

        float4* op = outp + px * 128;

        if (x0b == x0a) {
            // pair-b cols identical to pair-a cols (x1b==x1a follows)
            int co[2] = {x0a, x1a};
            cell_compute<NR, PB, 2, 0>(fmt, op, ro, co,
                                       waP, waQ, wbP, wbQ, uxa, wxa, uxb, wxb);
        } else if (x0b == x1a) {
            // shared middle column
            int co[3] = {x0a, x1a, x1b};
            cell_compute<NR, PB, 3, 1>(fmt, op, ro, co,
                                       waP, waQ, wbP, wbQ, uxa, wxa, uxb, wxb);
        } else {
            int co[4] = {x0a, x1a, x0b, x1b};
            cell_compute<NR, PB, 4, 2>(fmt, op, ro, co,
                                       waP, waQ, wbP, wbQ, uxa, wxa, uxb, wxb);
        }
    }
}

// One block per (pooled_row, roi). 128 threads x float4 = 512 channels.
// Row AND column tap dedup, both block-uniform dispatches.
__global__ __launch_bounds__(128, 8) void roi_pool_kernel(
    const float* __restrict__ fm,     // [38,50,512]
    const float* __restrict__ rois,   // [512,5] (0, x1, y1, x2, y2)
    float* __restrict__ out)          // [512,7,7,512]
{
    const int py  = blockIdx.x;       // 0..6
    const int roi = blockIdx.y;       // 0..511
    const int t   = threadIdx.x;      // channel group: c = 4*t

    const float* r = rois + roi * 5;
    const float x1n = r[1] * (1.0f / 800.0f);
    const float y1n = r[2] * (1.0f / 600.0f);
    const float x2n = r[3] * (1.0f / 800.0f);
    const float y2n = r[4] * (1.0f / 600.0f);
    const float dy = y2n - y1n;
    const float dx = x2n - x1n;

    // y taps for the two crop rows of this pooled row (block-uniform)
    int ra0, ra1, rb0, rb1;           // fm row offsets (row * FM_W)
    float wya, wyb;
    {
        const float tya = (float)(2 * py) * (1.0f / 13.0f);
        const float ysa = (y1n + tya * dy) * (float)(FM_H - 1);
        const float yfa = floorf(ysa);
        int y0 = (int)yfa; y0 = min(max(y0, 0), FM_H - 1);
        ra0 = y0 * FM_W;
        ra1 = min(y0 + 1, FM_H - 1) * FM_W;
        wya = ysa - yfa;

        const float tyb = (float)(2 * py + 1) * (1.0f / 13.0f);
        const float ysb = (y1n + tyb * dy) * (float)(FM_H - 1);
        const float yfb = floorf(ysb);
        int y1 = (int)yfb; y1 = min(max(y1, 0), FM_H - 1);
        rb0 = y1 * FM_W;
        rb1 = min(y1 + 1, FM_H - 1) * FM_W;
        wyb = ysb - yfb;
    }
    const float uya = 1.0f - wya;
    const float uyb = 1.0f - wyb;

    const float4* fmt = (const float4*)fm + t;
    float4* outp = (float4*)out + (size_t)((roi * POOL + py) * POOL) * 128 + t;

    // Row dedup dispatch (block-uniform, fixed for all 7 cells).
    if (rb0 == ra0) {
        // rows b identical to rows a
        run_row<2, 0>(fmt, outp, x1n, dx, ra0, ra1, 0, 0,
                      uya, wya, uyb, wyb);
    } else if (rb0 == ra1) {
        if (rb1 == rb0) {
            // both b taps land on row ra1
            run_row<2, 0>(fmt, outp, x1n, dx, ra0, ra1, 0, 0,
                          uya, wya, 0.0f, uyb + wyb);
        } else {
            // rows {ra0, ra1, rb1}; pair b uses (ra1, rb1)
            run_row<3, 1>(fmt, outp, x1n, dx, ra0, ra1, rb1, 0,
                          uya, wya, uyb, wyb);
        }
    } else {
        // fully distinct (rb1==rb0 clamp duplicates a load; still correct)
        run_row<4, 2>(fmt, outp, x1n, dx, ra0, ra1, rb0, rb1,
                      uya, wya, uyb, wyb);
    }
}

extern "C" void kernel_launch(void* const* d_in, const int* in_sizes, int n_in,
                              void* d_out, int out_size)
{
    const float* fm   = (const float*)d_in[0];   // feature_maps [1,38,50,512]
    const float* rois = (const float*)d_in[1];   // [512,5]
    float* out = (float*)d_out;                  // [1,512,7,7,512]

    dim3 grid(POOL, N_ROI);
    roi_pool_kernel<<<grid, 128>>>(fm, rois, out);
}